// round 8
// baseline (speedup 1.0000x reference)
#include <cuda_runtime.h>
#include <cstdint>

// ButterflyRotationLayer: R = B(d,d) @ B(d,d/2) @ ... @ B(d,2), d=4096, 12 stages.
//
// Split at k=64:
//   H = stages k=4096..128 : H[r,l] != 0 only when l == r (mod 64).
//       For fixed r6 = r&63, the 64 rows {r6+64*rh} share ONE 64x64 m-space
//       butterfly matrix Hhat_{r6}[rh, m].
//   T = stages k=64..2     : block-diagonal, 64 independent 64x64 matrices That_B.
// Exactly one l contributes per output element:
//   R[r6+64*rh, 64*B+cc] = Hhat_{r6}[rh, B] * That_B[r6, cc]
//
// Kernel 1 (128 blocks): builds the 128 small 64x64 matrices (sincos once per theta).
// Kernel 2 (2048 blocks): computes 8-row x 4KB tiles into SMEM, stores via
//   cp.async.bulk (TMA). Rationale: STG.128 costs ~12 LSU-cyc per 512B, which
//   was the measured bottleneck (~10.6K cyc/SM of pure store-issue). TMA bulk
//   stores move the 64MB on the async path; STS.128 to SMEM is ~4 cyc/512B on
//   the separate crossbar.

#define D 4096

// g_H[r*64 + m]  = Hhat_{r&63}[r>>6, m]
__device__ __align__(16) float g_H[D * 64];
// g_T[(B*64+rr)*64 + cc] = That_B[rr, cc]
__device__ __align__(16) float g_T[D * 64];

__device__ __forceinline__ uint32_t smem_u32(const void* p) {
    uint32_t a;
    asm("{ .reg .u64 t; cvta.to.shared.u64 t, %1; cvt.u32.u64 %0, t; }"
        : "=r"(a) : "l"(p));
    return a;
}

// ---------------------------------------------------------------------------
// Kernel 1: block b<64 -> head matrix Hhat_{r6=b}; b>=64 -> tail matrix That_{b-64}.
// M = I; each stage applies column Givens rotations (M <- M @ B_i).
// All 192 (c,s) pairs per block computed in parallel upfront.
// ---------------------------------------------------------------------------
__global__ __launch_bounds__(256) void butterfly_mats_kernel(const float* __restrict__ thetas) {
    __shared__ float sm[64][65];
    __shared__ float cs_c[6][32], cs_s[6][32];

    const int tid      = threadIdx.x;
    const int b        = blockIdx.x;
    const bool is_head = (b < 64);

    if (tid < 192) {
        const int ii   = tid >> 5;
        const int j    = tid & 31;
        const int half = 32 >> ii;
        const int bm   = j >> (5 - ii);
        const int jm   = j & (half - 1);
        const int p_loc = (bm << (6 - ii)) + jm;
        int theta_idx;
        if (is_head) {
            const int p    = b + (p_loc << 6);
            const int logk = 12 - ii;
            const int hh   = 2048 >> ii;
            theta_idx = ii * 2048 + (p >> logk) * hh + (p & ((1 << logk) - 1));
        } else {
            const int p    = ((b - 64) << 6) + p_loc;
            const int logk = 6 - ii;
            const int hh   = 32 >> ii;
            theta_idx = (ii + 6) * 2048 + (p >> logk) * hh + (p & ((1 << logk) - 1));
        }
        float s, c;
        sincosf(thetas[theta_idx], &s, &c);
        cs_c[ii][j] = c;
        cs_s[ii][j] = s;
    }

#pragma unroll
    for (int k = 0; k < 16; ++k) {
        const int e = tid + k * 256;
        sm[e >> 6][e & 63] = ((e >> 6) == (e & 63)) ? 1.0f : 0.0f;
    }
    __syncthreads();

    const int j = tid & 31;

#pragma unroll
    for (int ii = 0; ii < 6; ++ii) {
        const int half  = 32 >> ii;
        const int bm    = j >> (5 - ii);
        const int jm    = j & (half - 1);
        const int p_loc = (bm << (6 - ii)) + jm;
        const int q_loc = p_loc + half;
        const float c = cs_c[ii][j];
        const float s = cs_s[ii][j];
#pragma unroll
        for (int k = 0; k < 8; ++k) {
            const int row = (tid >> 5) + (k << 3);
            const float a  = sm[row][p_loc];
            const float bb = sm[row][q_loc];
            sm[row][p_loc] = c * a + s * bb;
            sm[row][q_loc] = c * bb - s * a;
        }
        __syncthreads();
    }

    if (is_head) {
#pragma unroll
        for (int k = 0; k < 16; ++k) {
            const int e  = tid + k * 256;
            const int rh = e >> 6;
            const int m  = e & 63;
            g_H[(b << 6) + (rh << 12) + m] = sm[rh][m];
        }
    } else {
        const int base = (b - 64) << 12;
#pragma unroll
        for (int k = 0; k < 16; ++k) {
            const int e = tid + k * 256;
            g_T[base + e] = sm[e >> 6][e & 63];
        }
    }
}

// ---------------------------------------------------------------------------
// Kernel 2: block (r6, g, ch) computes rows r = r6 + 64*(8g+jr), jr=0..7,
// columns [ch*1024, ch*1024+1024) into a 32KB SMEM tile, then TMA-bulk-stores
// the 8 x 4KB row segments. Per thread: 1 t-float4 load (shared across all 8
// rows), 8 h loads (MLP batched), 32 FFMA, 8 STS.128. No STG at all.
// ---------------------------------------------------------------------------
__global__ __launch_bounds__(256) void outer_tma_kernel(float* __restrict__ out) {
    __shared__ __align__(16) float sbuf[8][1024];   // 32 KB

    const int b   = blockIdx.x;                     // 0..2047
    const int tid = threadIdx.x;
    const int ch  = b & 3;                          // column chunk (1024 floats)
    const int r6  = (b >> 2) & 63;
    const int g   = b >> 8;                         // 0..7

    const int c4  = (ch << 8) | tid;                // float4 index within row
    const int c   = c4 << 2;
    const int B   = c >> 6;

    const int l = (B << 6) + r6;
    const float4 t = *reinterpret_cast<const float4*>(&g_T[(l << 6) + (c & 63)]);

    const int r0 = r6 + (g << 9);                   // rows r0 + 64*jr
    const float* __restrict__ hp = &g_H[(r0 << 6) + B];
    float h[8];
#pragma unroll
    for (int jr = 0; jr < 8; ++jr)
        h[jr] = hp[jr << 12];                       // stride 64 rows * 64 floats

#pragma unroll
    for (int jr = 0; jr < 8; ++jr) {
        const float hh = h[jr];
        *reinterpret_cast<float4*>(&sbuf[jr][tid << 2]) =
            make_float4(hh * t.x, hh * t.y, hh * t.z, hh * t.w);
    }
    __syncthreads();

    if (tid == 0) {
        asm volatile("fence.proxy.async.shared::cta;" ::: "memory");
#pragma unroll
        for (int jr = 0; jr < 8; ++jr) {
            const int r = r0 + (jr << 6);
            float* dst = out + ((size_t)r << 12) + (ch << 10);
            const uint32_t src = smem_u32(&sbuf[jr][0]);
            asm volatile(
                "cp.async.bulk.global.shared::cta.bulk_group [%0], [%1], %2;"
                :: "l"(dst), "r"(src), "n"(4096) : "memory");
        }
        asm volatile("cp.async.bulk.commit_group;" ::: "memory");
        asm volatile("cp.async.bulk.wait_group 0;" ::: "memory");
    }
    __syncthreads();   // SMEM must not be freed while TMA is still reading it
}

extern "C" void kernel_launch(void* const* d_in, const int* in_sizes, int n_in,
                              void* d_out, int out_size) {
    const float* thetas = (const float*)d_in[0];  // [12, 2048] fp32
    float* out = (float*)d_out;                   // [4096, 4096] fp32

    butterfly_mats_kernel<<<128, 256>>>(thetas);
    outer_tma_kernel<<<2048, 256>>>(out);
}